// round 8
// baseline (speedup 1.0000x reference)
#include <cuda_runtime.h>
#include <cuda_bf16.h>

#define NN 1024
#define DIM 128
#define HH 4
#define I_TILE 8
#define LOG2E 1.4426950408889634f

typedef unsigned long long u64;

// Scratch (device globals: no allocations allowed)
__device__ float g_L[NN * DIM];
__device__ float g_Rt[NN * DIM];          // transposed: [head][q][j][4], d = q*4+c
__device__ float g_Vp[NN * DIM];          // paired:     [head][j/2][d][2]
__device__ float g_La6[NN * HH];          // 0.6*log2e * sum_d a_d*L (exp2-ready)
__device__ float g_Ra6[NN * HH];
__device__ unsigned char g_adj8[128 * NN];// byte per (i-block, j): bit ii = adj

#define FMA2(acc, p, v) \
    asm("fma.rn.f32x2 %0, %1, %2, %0;" : "+l"(acc) : "l"(p), "l"(v))
#define ADD2(d, x, y) \
    asm("add.rn.f32x2 %0, %1, %2;" : "=l"(d) : "l"(x), "l"(y))
#define PACK2(d, lo, hi) \
    asm("mov.b64 %0, {%1, %2};" : "=l"(d) : "f"(lo), "f"(hi))
#define UNPACK2(lo, hi, s) \
    asm("mov.b64 {%0, %1}, %2;" : "=f"(lo), "=f"(hi) : "l"(s))

// ---------------------------------------------------------------------------
// Prep: y=0: L = h@W_l; y=1: Rt = transposed h@W_r; y=2: Vp = paired h@W_v;
// (plus La6/Ra6 pre-scaled by log2e). y=3 (first 128 x-blocks): pack adj bits.
// Grid (256, 4), block 128.
// ---------------------------------------------------------------------------
__global__ __launch_bounds__(128) void prep_kernel(
    const float* __restrict__ h,
    const int*   __restrict__ adj,
    const float* __restrict__ Wl,
    const float* __restrict__ Wr,
    const float* __restrict__ Wv,
    const float* __restrict__ a)
{
    int which = blockIdx.y;
    int tid = threadIdx.x;

    if (which == 3) {                    // adj bit-packing slice
        if (blockIdx.x >= 128) return;
        int i0 = blockIdx.x * 8;
#pragma unroll
        for (int jj = 0; jj < 8; jj++) {
            int j = tid + jj * 128;
            unsigned b = 0;
#pragma unroll
            for (int ii = 0; ii < 8; ii++)
                b |= (__ldg(&adj[(i0 + ii) * NN + j]) != 0 ? 1u : 0u) << ii;
            g_adj8[blockIdx.x * NN + j] = (unsigned char)b;
        }
        return;
    }

    const float* W = (which == 0) ? Wl : (which == 1) ? Wr : Wv;
    int i0 = blockIdx.x * 4;

    __shared__ float h_s[4 * DIM];
#pragma unroll
    for (int q = 0; q < 4; q++)
        h_s[tid + q * 128] = h[i0 * DIM + tid + q * 128];
    __syncthreads();

    float acc[4] = {0.f, 0.f, 0.f, 0.f};
    const float4* h4 = reinterpret_cast<const float4*>(h_s);
#pragma unroll 8
    for (int k4 = 0; k4 < 32; k4++) {
        float w0 = __ldg(&W[(k4 * 4 + 0) * DIM + tid]);
        float w1 = __ldg(&W[(k4 * 4 + 1) * DIM + tid]);
        float w2 = __ldg(&W[(k4 * 4 + 2) * DIM + tid]);
        float w3 = __ldg(&W[(k4 * 4 + 3) * DIM + tid]);
#pragma unroll
        for (int r = 0; r < 4; r++) {
            float4 hv = h4[r * 32 + k4];
            acc[r] += hv.x * w0 + hv.y * w1 + hv.z * w2 + hv.w * w3;
        }
    }

    int head = tid >> 5, d = tid & 31;
    if (which == 0) {
#pragma unroll
        for (int r = 0; r < 4; r++) g_L[(i0 + r) * DIM + tid] = acc[r];
    } else if (which == 1) {
        // transposed store: (i, col=tid) -> g_Rt[((head*8+q)*NN + i)*4 + c]
        int q = d >> 2, c = d & 3;
        float* base = &g_Rt[(size_t)((head * 8 + q) * NN) * 4 + c];
#pragma unroll
        for (int r = 0; r < 4; r++) base[(i0 + r) * 4] = acc[r];
    } else {
        // paired store: {v[2k][d], v[2k+1][d]} at g_Vp[((head*512+k)*32+d)*2]
#pragma unroll
        for (int pr = 0; pr < 2; pr++) {
            float2 pv = make_float2(acc[2 * pr], acc[2 * pr + 1]);
            *reinterpret_cast<float2*>(
                &g_Vp[(size_t)((head * 512 + (i0 >> 1) + pr) * 32 + d) * 2]) = pv;
        }
    }

    if (which < 2) {
        float av = 0.6f * LOG2E * __ldg(&a[d]);
        float* A6 = (which == 0) ? g_La6 : g_Ra6;
#pragma unroll
        for (int r = 0; r < 4; r++) {
            float v = av * acc[r];
#pragma unroll
            for (int o = 16; o; o >>= 1) v += __shfl_xor_sync(0xffffffffu, v, o);
            if (d == 0) A6[(i0 + r) * HH + head] = v;
        }
    }
}

// ---------------------------------------------------------------------------
// Main fused kernel. Grid 128 (I_TILE=8 rows each), block 512 = 16 warps.
// Warp w: head = w&3, js = w>>2. Per t, warp handles j = t*128 + js*32 + lane
// for ALL 8 i-rows. R/Vp/adj8 read directly from gmem (L2/L1-resident).
// e-phase: packed f32x2 (ADD2 on FMA pipe, abs via LOP3 on ALU pipe, FFMA2);
// agg-phase: lane owns d, packed f32x2 FFMA2. Max-free base-2 softmax.
// ---------------------------------------------------------------------------
__global__ __launch_bounds__(512) void gat_main(
    const float* __restrict__ a,
    const float* __restrict__ ln_g,
    const float* __restrict__ ln_b,
    float*       __restrict__ out)
{
    __shared__ __align__(16) float l_s[I_TILE * DIM];
    __shared__ __align__(16) float p_s[16 * I_TILE * 32];
    __shared__ float sl_s[16 * I_TILE];

    int tid  = threadIdx.x;
    int w    = tid >> 5, lane = tid & 31;
    int head = w & 3,    js   = w >> 2;      // js in 0..3
    int i0   = blockIdx.x * I_TILE;

    // 0.4*log2e * a_d, packed into 16 f32x2 pairs (warp-uniform)
    u64 ar2[16];
#pragma unroll
    for (int d2 = 0; d2 < 16; d2++) {
        float c0 = (0.4f * LOG2E) * __ldg(&a[2 * d2]);
        float c1 = (0.4f * LOG2E) * __ldg(&a[2 * d2 + 1]);
        PACK2(ar2[d2], c0, c1);
    }

    for (int idx = tid; idx < I_TILE * DIM; idx += 512)
        l_s[idx] = g_L[i0 * DIM + idx];

    float la[I_TILE], sl[I_TILE];
    u64 acc2[I_TILE];
#pragma unroll
    for (int ii = 0; ii < I_TILE; ii++) {
        la[ii]   = __ldg(&g_La6[(i0 + ii) * HH + head]);
        sl[ii]   = 0.f;
        acc2[ii] = 0ull;                     // packed {0.f, 0.f}
    }
    __syncthreads();   // l_s visible

    const ulonglong2* Rt2 = reinterpret_cast<const ulonglong2*>(g_Rt);
    const double*     Vp  = reinterpret_cast<const double*>(g_Vp);
    float* myp = &p_s[w * I_TILE * 32];

    for (int t = 0; t < 8; t++) {
        int j0   = t * 128;
        int jcol = j0 + js * 32 + lane;      // this lane's j

        // ---- front-batched loads (all L2/L1 hits) ----
        u64 rp[16];                          // 8 q x 2 pairs of r values
#pragma unroll
        for (int q = 0; q < 8; q++) {
            ulonglong2 rq = __ldg(&Rt2[(head * 8 + q) * NN + jcol]);
            rp[2 * q] = rq.x; rp[2 * q + 1] = rq.y;
        }
        float ra = __ldg(&g_Ra6[jcol * HH + head]);
        unsigned b = __ldg(&g_adj8[blockIdx.x * NN + jcol]);

        // ---- e phase: p = maskbit ? 2^e : 0 ----
#pragma unroll
        for (int ii = 0; ii < I_TILE; ii++) {
            const ulonglong2* lp = reinterpret_cast<const ulonglong2*>(&l_s[ii * DIM + head * 32]);
            u64 e01 = 0ull, e23 = 0ull;
#pragma unroll
            for (int q = 0; q < 8; q++) {
                ulonglong2 l2 = lp[q];
                u64 s0, s1;
                ADD2(s0, l2.x, rp[2 * q]);
                ADD2(s1, l2.y, rp[2 * q + 1]);
                s0 &= 0x7FFFFFFF7FFFFFFFull;     // |.| on both halves (ALU pipe)
                s1 &= 0x7FFFFFFF7FFFFFFFull;
                FMA2(e01, ar2[2 * q], s0);
                FMA2(e23, ar2[2 * q + 1], s1);
            }
            float e0, e1, e2, e3;
            UNPACK2(e0, e1, e01);
            UNPACK2(e2, e3, e23);
            float e = la[ii] + ra + ((e0 + e1) + (e2 + e3));
            float p;
            asm("ex2.approx.f32 %0, %1;" : "=f"(p) : "f"(e));
            p = (b & (1u << ii)) ? p : 0.f;
            sl[ii] += p;
            myp[ii * 32 + lane] = p;
        }
        __syncwarp();

        // ---- agg phase: lane owns d; packed pairs over j, FFMA2 ----
        int jp0 = (j0 + js * 32) >> 1;       // j-pair base for this warp
#pragma unroll
        for (int q = 0; q < 4; q++) {
            const double* vp = &Vp[(size_t)(head * 512 + jp0 + q * 4) * 32 + lane];
            u64 v0 = __double_as_longlong(__ldg(vp + 0 * 32));
            u64 v1 = __double_as_longlong(__ldg(vp + 1 * 32));
            u64 v2 = __double_as_longlong(__ldg(vp + 2 * 32));
            u64 v3 = __double_as_longlong(__ldg(vp + 3 * 32));
#pragma unroll
            for (int ii = 0; ii < I_TILE; ii++) {
                ulonglong2 pA = *reinterpret_cast<const ulonglong2*>(&myp[ii * 32 + q * 8]);
                ulonglong2 pB = *reinterpret_cast<const ulonglong2*>(&myp[ii * 32 + q * 8 + 4]);
                FMA2(acc2[ii], pA.x, v0);
                FMA2(acc2[ii], pA.y, v1);
                FMA2(acc2[ii], pB.x, v2);
                FMA2(acc2[ii], pB.y, v3);
            }
        }
        __syncwarp();
    }

    // ---- horizontal unpack of packed accumulators ----
    float accA[I_TILE];
#pragma unroll
    for (int ii = 0; ii < I_TILE; ii++) {
        float lo, hi;
        UNPACK2(lo, hi, acc2[ii]);
        accA[ii] = lo + hi;
    }

    // ---- cross-warp (js) reduction ----
#pragma unroll
    for (int ii = 0; ii < I_TILE; ii++) {
        float S = sl[ii];
#pragma unroll
        for (int o = 16; o; o >>= 1) S += __shfl_xor_sync(0xffffffffu, S, o);
        sl[ii] = S;
    }
    __syncthreads();                 // everyone done with p_s as p-buffer
#pragma unroll
    for (int ii = 0; ii < I_TILE; ii++) {
        myp[ii * 32 + lane] = accA[ii];          // reuse p_s as acc buffer
        if (lane == 0) sl_s[w * I_TILE + ii] = sl[ii];
    }
    __syncthreads();

    // warp w: head' = w&3, covers ii = (w>>2) and (w>>2)+4
#pragma unroll
    for (int r = 0; r < 2; r++) {
        int ii = (w >> 2) + r * 4;
        int hh = w & 3;
        float acc = 0.f, S = 0.f;
#pragma unroll
        for (int g = 0; g < 4; g++) {
            acc += p_s[((g * 4 + hh) * I_TILE + ii) * 32 + lane];
            S   += sl_s[(g * 4 + hh) * I_TILE + ii];
        }
        l_s[ii * DIM + hh * 32 + lane] = acc * __frcp_rn(S);
    }
    __syncthreads();

    // LayerNorm + ReLU: warps 0..7 handle rows 0..7
    if (w < I_TILE) {
        int i = w;
        float v0 = l_s[i * DIM + lane];
        float v1 = l_s[i * DIM + 32 + lane];
        float v2 = l_s[i * DIM + 64 + lane];
        float v3 = l_s[i * DIM + 96 + lane];
        float sm = (v0 + v1) + (v2 + v3);
        float sq = v0 * v0 + v1 * v1 + v2 * v2 + v3 * v3;
#pragma unroll
        for (int o = 16; o; o >>= 1) {
            sm += __shfl_xor_sync(0xffffffffu, sm, o);
            sq += __shfl_xor_sync(0xffffffffu, sq, o);
        }
        float mean = sm * (1.f / 128.f);
        float var  = sq * (1.f / 128.f) - mean * mean;
        float rstd = rsqrtf(var + 1e-5f);
        float vals[4] = {v0, v1, v2, v3};
#pragma unroll
        for (int k = 0; k < 4; k++) {
            int c = 32 * k + lane;
            float y = (vals[k] - mean) * rstd * __ldg(&ln_g[c]) + __ldg(&ln_b[c]);
            out[(i0 + i) * DIM + c] = fmaxf(y, 0.f);
        }
    }
}

extern "C" void kernel_launch(void* const* d_in, const int* in_sizes, int n_in,
                              void* d_out, int out_size)
{
    const float* h   = (const float*)d_in[0];
    const int*   adj = (const int*)  d_in[1];
    const float* Wl  = (const float*)d_in[2];
    const float* Wr  = (const float*)d_in[3];
    const float* Wv  = (const float*)d_in[4];
    const float* a   = (const float*)d_in[5];
    const float* g   = (const float*)d_in[6];
    const float* b   = (const float*)d_in[7];

    prep_kernel<<<dim3(256, 4), 128>>>(h, adj, Wl, Wr, Wv, a);
    gat_main<<<NN / I_TILE, 512>>>(a, g, b, (float*)d_out);
}

// round 9
// speedup vs baseline: 1.0062x; 1.0062x over previous
#include <cuda_runtime.h>
#include <cuda_bf16.h>

#define NN 1024
#define DIM 128
#define HH 4
#define I_TILE 8
#define LOG2E 1.4426950408889634f

typedef unsigned long long u64;

// Scratch (device globals: no allocations allowed)
__device__ float g_L[NN * DIM];
__device__ float g_Rt[NN * DIM];          // transposed: [head][q][j][4], d = q*4+c
__device__ float g_Vp[NN * DIM];          // paired:     [head][j/2][d][2]
__device__ float g_La6[NN * HH];          // 0.6*log2e * sum_d a_d*L (exp2-ready)
__device__ float g_Ra6[NN * HH];
__device__ unsigned char g_adj8[128 * NN];// byte per (i-block, j): bit ii = adj

#define FMA2(acc, p, v) \
    asm("fma.rn.f32x2 %0, %1, %2, %0;" : "+l"(acc) : "l"(p), "l"(v))
#define ADD2(d, x, y) \
    asm("add.rn.f32x2 %0, %1, %2;" : "=l"(d) : "l"(x), "l"(y))
#define PACK2(d, lo, hi) \
    asm("mov.b64 %0, {%1, %2};" : "=l"(d) : "f"(lo), "f"(hi))
#define UNPACK2(lo, hi, s) \
    asm("mov.b64 {%0, %1}, %2;" : "=f"(lo), "=f"(hi) : "l"(s))

// ---------------------------------------------------------------------------
// Prep: y=0: L = h@W_l; y=1: Rt = transposed h@W_r; y=2: Vp = paired h@W_v;
// (plus La6/Ra6 pre-scaled by log2e). y=3 (first 128 x-blocks): pack adj bits.
// Grid (256, 4), block 128.
// ---------------------------------------------------------------------------
__global__ __launch_bounds__(128) void prep_kernel(
    const float* __restrict__ h,
    const int*   __restrict__ adj,
    const float* __restrict__ Wl,
    const float* __restrict__ Wr,
    const float* __restrict__ Wv,
    const float* __restrict__ a)
{
    int which = blockIdx.y;
    int tid = threadIdx.x;

    if (which == 3) {                    // adj bit-packing slice
        if (blockIdx.x >= 128) return;
        int i0 = blockIdx.x * 8;
#pragma unroll
        for (int jj = 0; jj < 8; jj++) {
            int j = tid + jj * 128;
            unsigned b = 0;
#pragma unroll
            for (int ii = 0; ii < 8; ii++)
                b |= (__ldg(&adj[(i0 + ii) * NN + j]) != 0 ? 1u : 0u) << ii;
            g_adj8[blockIdx.x * NN + j] = (unsigned char)b;
        }
        return;
    }

    const float* W = (which == 0) ? Wl : (which == 1) ? Wr : Wv;
    int i0 = blockIdx.x * 4;

    __shared__ float h_s[4 * DIM];
#pragma unroll
    for (int q = 0; q < 4; q++)
        h_s[tid + q * 128] = h[i0 * DIM + tid + q * 128];
    __syncthreads();

    float acc[4] = {0.f, 0.f, 0.f, 0.f};
    const float4* h4 = reinterpret_cast<const float4*>(h_s);
#pragma unroll 8
    for (int k4 = 0; k4 < 32; k4++) {
        float w0 = __ldg(&W[(k4 * 4 + 0) * DIM + tid]);
        float w1 = __ldg(&W[(k4 * 4 + 1) * DIM + tid]);
        float w2 = __ldg(&W[(k4 * 4 + 2) * DIM + tid]);
        float w3 = __ldg(&W[(k4 * 4 + 3) * DIM + tid]);
#pragma unroll
        for (int r = 0; r < 4; r++) {
            float4 hv = h4[r * 32 + k4];
            acc[r] += hv.x * w0 + hv.y * w1 + hv.z * w2 + hv.w * w3;
        }
    }

    int head = tid >> 5, d = tid & 31;
    if (which == 0) {
#pragma unroll
        for (int r = 0; r < 4; r++) g_L[(i0 + r) * DIM + tid] = acc[r];
    } else if (which == 1) {
        // transposed store: (i, col=tid) -> g_Rt[((head*8+q)*NN + i)*4 + c]
        int q = d >> 2, c = d & 3;
        float* base = &g_Rt[(size_t)((head * 8 + q) * NN) * 4 + c];
#pragma unroll
        for (int r = 0; r < 4; r++) base[(i0 + r) * 4] = acc[r];
    } else {
        // paired store: {v[2k][d], v[2k+1][d]} at g_Vp[((head*512+k)*32+d)*2]
#pragma unroll
        for (int pr = 0; pr < 2; pr++) {
            float2 pv = make_float2(acc[2 * pr], acc[2 * pr + 1]);
            *reinterpret_cast<float2*>(
                &g_Vp[(size_t)((head * 512 + (i0 >> 1) + pr) * 32 + d) * 2]) = pv;
        }
    }

    if (which < 2) {
        float av = 0.6f * LOG2E * __ldg(&a[d]);
        float* A6 = (which == 0) ? g_La6 : g_Ra6;
#pragma unroll
        for (int r = 0; r < 4; r++) {
            float v = av * acc[r];
#pragma unroll
            for (int o = 16; o; o >>= 1) v += __shfl_xor_sync(0xffffffffu, v, o);
            if (d == 0) A6[(i0 + r) * HH + head] = v;
        }
    }
}

// ---------------------------------------------------------------------------
// Main fused kernel. Grid 128 (I_TILE=8 rows each), block 512 = 16 warps.
// Warp w: head = w&3, js = w>>2. Per t, warp handles j = t*128 + js*32 + lane
// for ALL 8 i-rows.
// Register diet: ar in smem (per-q LDS.128), r prefetched depth-2, v hoisted
// in two batches -> all gmem latency overlapped. Max-free base-2 softmax.
// ---------------------------------------------------------------------------
__global__ __launch_bounds__(512) void gat_main(
    const float* __restrict__ a,
    const float* __restrict__ ln_g,
    const float* __restrict__ ln_b,
    float*       __restrict__ out)
{
    __shared__ __align__(16) float l_s[I_TILE * DIM];
    __shared__ __align__(16) float p_s[16 * I_TILE * 32];
    __shared__ __align__(16) u64   ar_s[16];
    __shared__ float sl_s[16 * I_TILE];

    int tid  = threadIdx.x;
    int w    = tid >> 5, lane = tid & 31;
    int head = w & 3,    js   = w >> 2;      // js in 0..3
    int i0   = blockIdx.x * I_TILE;

    // 0.4*log2e * a_d packed pairs -> shared (one copy, warp-uniform LDS later)
    if (tid < 16) {
        float c0 = (0.4f * LOG2E) * __ldg(&a[2 * tid]);
        float c1 = (0.4f * LOG2E) * __ldg(&a[2 * tid + 1]);
        u64 pk; PACK2(pk, c0, c1);
        ar_s[tid] = pk;
    }

    for (int idx = tid; idx < I_TILE * DIM; idx += 512)
        l_s[idx] = g_L[i0 * DIM + idx];

    float la[I_TILE], sl[I_TILE];
    u64 acc2[I_TILE];
#pragma unroll
    for (int ii = 0; ii < I_TILE; ii++) {
        la[ii]   = __ldg(&g_La6[(i0 + ii) * HH + head]);
        sl[ii]   = 0.f;
        acc2[ii] = 0ull;                     // packed {0.f, 0.f}
    }
    __syncthreads();   // l_s + ar_s visible

    const ulonglong2* Rt2 = reinterpret_cast<const ulonglong2*>(g_Rt);
    const double*     Vp  = reinterpret_cast<const double*>(g_Vp);
    float* myp = &p_s[w * I_TILE * 32];
    const float* lbase = &l_s[head * 32];

    for (int t = 0; t < 8; t++) {
        int jcol = t * 128 + js * 32 + lane;     // this lane's j
        int jpb  = head * 512 + t * 64 + js * 16;// j-pair base for this warp

        // ---- stage-top loads: adj, ra, r prefetch (depth 2), first v half ----
        ulonglong2 rb0 = __ldg(&Rt2[(head * 8 + 0) * NN + jcol]);
        ulonglong2 rb1 = __ldg(&Rt2[(head * 8 + 1) * NN + jcol]);
        float ra = __ldg(&g_Ra6[jcol * HH + head]);
        unsigned b = __ldg(&g_adj8[blockIdx.x * NN + jcol]);
        u64 vh[8];
#pragma unroll
        for (int k = 0; k < 8; k++)
            vh[k] = __double_as_longlong(__ldg(&Vp[(size_t)(jpb + k) * 32 + lane]));

        // ---- e accumulators seeded with {la+ra, 0} ----
        u64 e_acc[I_TILE];
#pragma unroll
        for (int ii = 0; ii < I_TILE; ii++)
            PACK2(e_acc[ii], la[ii] + ra, 0.f);

        // ---- e phase: q-outer, ii-inner; ar from smem; r rolling prefetch ----
#pragma unroll
        for (int q = 0; q < 8; q++) {
            ulonglong2 rc = rb0;
            rb0 = rb1;
            if (q < 6) rb1 = __ldg(&Rt2[(head * 8 + q + 2) * NN + jcol]);
            ulonglong2 arq = *reinterpret_cast<const ulonglong2*>(&ar_s[2 * q]);
#pragma unroll
            for (int ii = 0; ii < I_TILE; ii++) {
                ulonglong2 l2 = *reinterpret_cast<const ulonglong2*>(&lbase[ii * DIM + 4 * q]);
                u64 s0, s1;
                ADD2(s0, l2.x, rc.x);
                ADD2(s1, l2.y, rc.y);
                s0 &= 0x7FFFFFFF7FFFFFFFull;     // |.| both halves (ALU pipe)
                s1 &= 0x7FFFFFFF7FFFFFFFull;
                FMA2(e_acc[ii], arq.x, s0);
                FMA2(e_acc[ii], arq.y, s1);
            }
        }

        // ---- epilogue: p = maskbit ? 2^e : 0 ----
#pragma unroll
        for (int ii = 0; ii < I_TILE; ii++) {
            float lo, hi;
            UNPACK2(lo, hi, e_acc[ii]);
            float e = lo + hi;
            float p;
            asm("ex2.approx.f32 %0, %1;" : "=f"(p) : "f"(e));
            p = (b & (1u << ii)) ? p : 0.f;
            sl[ii] += p;
            myp[ii * 32 + lane] = p;
        }

        // second v half issued before the handoff barrier (hidden by agg 1st half)
        u64 vh2[8];
#pragma unroll
        for (int k = 0; k < 8; k++)
            vh2[k] = __double_as_longlong(__ldg(&Vp[(size_t)(jpb + 8 + k) * 32 + lane]));
        __syncwarp();

        // ---- agg phase: lane owns d; packed pairs over j, FFMA2 ----
#pragma unroll
        for (int q4 = 0; q4 < 4; q4++) {
            u64 v0 = (q4 < 2) ? vh[q4 * 4 + 0] : vh2[(q4 - 2) * 4 + 0];
            u64 v1 = (q4 < 2) ? vh[q4 * 4 + 1] : vh2[(q4 - 2) * 4 + 1];
            u64 v2 = (q4 < 2) ? vh[q4 * 4 + 2] : vh2[(q4 - 2) * 4 + 2];
            u64 v3 = (q4 < 2) ? vh[q4 * 4 + 3] : vh2[(q4 - 2) * 4 + 3];
#pragma unroll
            for (int ii = 0; ii < I_TILE; ii++) {
                ulonglong2 pA = *reinterpret_cast<const ulonglong2*>(&myp[ii * 32 + q4 * 8]);
                ulonglong2 pB = *reinterpret_cast<const ulonglong2*>(&myp[ii * 32 + q4 * 8 + 4]);
                FMA2(acc2[ii], pA.x, v0);
                FMA2(acc2[ii], pA.y, v1);
                FMA2(acc2[ii], pB.x, v2);
                FMA2(acc2[ii], pB.y, v3);
            }
        }
        __syncwarp();
    }

    // ---- horizontal unpack of packed accumulators ----
    float accA[I_TILE];
#pragma unroll
    for (int ii = 0; ii < I_TILE; ii++) {
        float lo, hi;
        UNPACK2(lo, hi, acc2[ii]);
        accA[ii] = lo + hi;
    }

    // ---- cross-warp (js) reduction ----
#pragma unroll
    for (int ii = 0; ii < I_TILE; ii++) {
        float S = sl[ii];
#pragma unroll
        for (int o = 16; o; o >>= 1) S += __shfl_xor_sync(0xffffffffu, S, o);
        sl[ii] = S;
    }
    __syncthreads();                 // everyone done with p_s as p-buffer
#pragma unroll
    for (int ii = 0; ii < I_TILE; ii++) {
        myp[ii * 32 + lane] = accA[ii];          // reuse p_s as acc buffer
        if (lane == 0) sl_s[w * I_TILE + ii] = sl[ii];
    }
    __syncthreads();

    // warp w: head' = w&3, covers ii = (w>>2) and (w>>2)+4
#pragma unroll
    for (int r = 0; r < 2; r++) {
        int ii = (w >> 2) + r * 4;
        int hh = w & 3;
        float acc = 0.f, S = 0.f;
#pragma unroll
        for (int g = 0; g < 4; g++) {
            acc += p_s[((g * 4 + hh) * I_TILE + ii) * 32 + lane];
            S   += sl_s[(g * 4 + hh) * I_TILE + ii];
        }
        l_s[ii * DIM + hh * 32 + lane] = acc * __frcp_rn(S);
    }
    __syncthreads();

    // LayerNorm + ReLU: warps 0..7 handle rows 0..7
    if (w < I_TILE) {
        int i = w;
        float v0 = l_s[i * DIM + lane];
        float v1 = l_s[i * DIM + 32 + lane];
        float v2 = l_s[i * DIM + 64 + lane];
        float v3 = l_s[i * DIM + 96 + lane];
        float sm = (v0 + v1) + (v2 + v3);
        float sq = v0 * v0 + v1 * v1 + v2 * v2 + v3 * v3;
#pragma unroll
        for (int o = 16; o; o >>= 1) {
            sm += __shfl_xor_sync(0xffffffffu, sm, o);
            sq += __shfl_xor_sync(0xffffffffu, sq, o);
        }
        float mean = sm * (1.f / 128.f);
        float var  = sq * (1.f / 128.f) - mean * mean;
        float rstd = rsqrtf(var + 1e-5f);
        float vals[4] = {v0, v1, v2, v3};
#pragma unroll
        for (int k = 0; k < 4; k++) {
            int c = 32 * k + lane;
            float y = (vals[k] - mean) * rstd * __ldg(&ln_g[c]) + __ldg(&ln_b[c]);
            out[(i0 + i) * DIM + c] = fmaxf(y, 0.f);
        }
    }
}

extern "C" void kernel_launch(void* const* d_in, const int* in_sizes, int n_in,
                              void* d_out, int out_size)
{
    const float* h   = (const float*)d_in[0];
    const int*   adj = (const int*)  d_in[1];
    const float* Wl  = (const float*)d_in[2];
    const float* Wr  = (const float*)d_in[3];
    const float* Wv  = (const float*)d_in[4];
    const float* a   = (const float*)d_in[5];
    const float* g   = (const float*)d_in[6];
    const float* b   = (const float*)d_in[7];

    prep_kernel<<<dim3(256, 4), 128>>>(h, adj, Wl, Wr, Wv, a);
    gat_main<<<NN / I_TILE, 512>>>(a, g, b, (float*)d_out);
}

// round 10
// speedup vs baseline: 1.0116x; 1.0054x over previous
#include <cuda_runtime.h>
#include <cuda_fp16.h>

#define NN 1024
#define DIM 128
#define HH 4
#define I_TILE 8
#define LOG2E 1.4426950408889634f

typedef unsigned long long u64;
typedef unsigned int u32;

// Scratch (device globals: no allocations allowed)
__device__ __half g_Lh[NN * DIM];          // fp16 L, row-major [i][head*32+d]
__device__ __half g_Rh[NN * DIM];          // fp16 R, [head*4+qg][j][8 halves]
__device__ float  g_Vp[NN * DIM];          // paired: [head][j/2][d][2]
__device__ float  g_La6[NN * HH];          // 0.6*log2e * sum_d a_d*L (exp2-ready)
__device__ float  g_Ra6[NN * HH];
__device__ unsigned char g_adj8[128 * NN]; // byte per (i-block, j): bit ii = adj

#define FMA2(acc, p, v) \
    asm("fma.rn.f32x2 %0, %1, %2, %0;" : "+l"(acc) : "l"(p), "l"(v))
#define PACK2(d, lo, hi) \
    asm("mov.b64 %0, {%1, %2};" : "=l"(d) : "f"(lo), "f"(hi))
#define UNPACK2(lo, hi, s) \
    asm("mov.b64 {%0, %1}, %2;" : "=f"(lo), "=f"(hi) : "l"(s))
#define HADD2(d, x, y) \
    asm("add.rn.f16x2 %0, %1, %2;" : "=r"(d) : "r"(x), "r"(y))
#define HFMA2(acc, m, x) \
    asm("fma.rn.f16x2 %0, %1, %2, %0;" : "+r"(acc) : "r"(m), "r"(x))

// ---------------------------------------------------------------------------
// Prep: y=0: Lh = fp16(h@W_l); y=1: Rh = fp16 transposed h@W_r; y=2: Vp;
// plus La6/Ra6 (pre-scaled by 0.6*log2e). y=3: pack adj bits.
// Grid (128, 4), block 128. GEMM slices: 8 rows x 128 cols per CTA.
// ---------------------------------------------------------------------------
__global__ __launch_bounds__(128) void prep_kernel(
    const float* __restrict__ h,
    const int*   __restrict__ adj,
    const float* __restrict__ Wl,
    const float* __restrict__ Wr,
    const float* __restrict__ Wv,
    const float* __restrict__ a)
{
    int which = blockIdx.y;
    int tid = threadIdx.x;

    if (which == 3) {                    // adj bit-packing slice
        int i0 = blockIdx.x * 8;
#pragma unroll
        for (int jj = 0; jj < 8; jj++) {
            int j = tid + jj * 128;
            unsigned b = 0;
#pragma unroll
            for (int ii = 0; ii < 8; ii++)
                b |= (__ldg(&adj[(i0 + ii) * NN + j]) != 0 ? 1u : 0u) << ii;
            g_adj8[blockIdx.x * NN + j] = (unsigned char)b;
        }
        return;
    }

    const float* W = (which == 0) ? Wl : (which == 1) ? Wr : Wv;
    int i0 = blockIdx.x * 8;

    __shared__ float h_s[8 * DIM];
#pragma unroll
    for (int q = 0; q < 8; q++)
        h_s[tid + q * 128] = h[i0 * DIM + tid + q * 128];
    __syncthreads();

    float acc[8] = {0.f, 0.f, 0.f, 0.f, 0.f, 0.f, 0.f, 0.f};
    const float4* h4 = reinterpret_cast<const float4*>(h_s);
#pragma unroll 4
    for (int k4 = 0; k4 < 32; k4++) {
        float w0 = __ldg(&W[(k4 * 4 + 0) * DIM + tid]);
        float w1 = __ldg(&W[(k4 * 4 + 1) * DIM + tid]);
        float w2 = __ldg(&W[(k4 * 4 + 2) * DIM + tid]);
        float w3 = __ldg(&W[(k4 * 4 + 3) * DIM + tid]);
#pragma unroll
        for (int r = 0; r < 8; r++) {
            float4 hv = h4[r * 32 + k4];
            acc[r] += hv.x * w0 + hv.y * w1 + hv.z * w2 + hv.w * w3;
        }
    }

    int head = tid >> 5, d = tid & 31;
    if (which == 0) {
#pragma unroll
        for (int r = 0; r < 8; r++)
            g_Lh[(i0 + r) * DIM + tid] = __float2half_rn(acc[r]);
    } else if (which == 1) {
        // fp16 transposed: (j, head, d) -> g_Rh[((head*4+qg)*NN + j)*8 + slot]
        int qg = d >> 3, slot = d & 7;
        __half* base = &g_Rh[(size_t)((head * 4 + qg) * NN) * 8 + slot];
#pragma unroll
        for (int r = 0; r < 8; r++) base[(i0 + r) * 8] = __float2half_rn(acc[r]);
    } else {
        // paired store: {v[2k][d], v[2k+1][d]} at g_Vp[((head*512+k)*32+d)*2]
#pragma unroll
        for (int pr = 0; pr < 4; pr++) {
            float2 pv = make_float2(acc[2 * pr], acc[2 * pr + 1]);
            *reinterpret_cast<float2*>(
                &g_Vp[(size_t)((head * 512 + (i0 >> 1) + pr) * 32 + d) * 2]) = pv;
        }
    }

    if (which < 2) {
        float av = 0.6f * LOG2E * __ldg(&a[d]);
        float* A6 = (which == 0) ? g_La6 : g_Ra6;
#pragma unroll
        for (int r = 0; r < 8; r++) {
            float v = av * acc[r];
#pragma unroll
            for (int o = 16; o; o >>= 1) v += __shfl_xor_sync(0xffffffffu, v, o);
            if (d == 0) A6[(i0 + r) * HH + head] = v;
        }
    }
}

// ---------------------------------------------------------------------------
// Main fused kernel. Grid 128 (I_TILE=8 rows each), block 512 = 16 warps.
// Warp w: head = w&3, js = w>>2; per t handles j = t*128+js*32+lane, all 8 i.
// e-phase in fp16x2 (HADD2 + LOP abs + HFMA2, full-rate on FMA pipe) with
// per-half 4-deep accumulation; linear term + softmax in fp32.
// agg-phase in packed f32x2. Max-free base-2 softmax; mask -> p = 0.
// ---------------------------------------------------------------------------
__global__ __launch_bounds__(512) void gat_main(
    const float* __restrict__ a,
    const float* __restrict__ ln_g,
    const float* __restrict__ ln_b,
    float*       __restrict__ out)
{
    __shared__ __align__(16) __half l_sh[I_TILE * DIM];   // fp16 l rows
    __shared__ __align__(16) float  p_s[16 * I_TILE * 32];// [warp][ii][j]
    __shared__ __align__(16) float  o_s[I_TILE * DIM];    // final agg buffer
    __shared__ float sl_s[16 * I_TILE];

    int tid  = threadIdx.x;
    int w    = tid >> 5, lane = tid & 31;
    int head = w & 3,    js   = w >> 2;      // js in 0..3
    int i0   = blockIdx.x * I_TILE;

    // 0.4*log2e * a packed as 16 fp16x2 (d-pairs), warp-uniform in regs
    u32 ar2h[16];
#pragma unroll
    for (int s = 0; s < 16; s++) {
        __half2 hp = __floats2half2_rn((0.4f * LOG2E) * __ldg(&a[2 * s]),
                                       (0.4f * LOG2E) * __ldg(&a[2 * s + 1]));
        ar2h[s] = *reinterpret_cast<u32*>(&hp);
    }

    if (tid < 128)       // stage fp16 l rows: 8 x 256B
        reinterpret_cast<uint4*>(l_sh)[tid] =
            __ldg(&reinterpret_cast<const uint4*>(g_Lh)[i0 * (DIM / 8) + tid]);

    float la[I_TILE], sl[I_TILE];
    u64 acc2[I_TILE];
#pragma unroll
    for (int ii = 0; ii < I_TILE; ii++) {
        la[ii]   = __ldg(&g_La6[(i0 + ii) * HH + head]);
        sl[ii]   = 0.f;
        acc2[ii] = 0ull;
    }
    __syncthreads();   // l_sh visible

    const uint4*  Rh4 = reinterpret_cast<const uint4*>(g_Rh);
    const double* Vp  = reinterpret_cast<const double*>(g_Vp);
    float* myp = &p_s[w * I_TILE * 32];

    for (int t = 0; t < 8; t++) {
        int jcol = t * 128 + js * 32 + lane;      // this lane's j
        int jpb  = head * 512 + t * 64 + js * 16; // j-pair base for this warp

        // ---- stage-top loads: r (4x LDG.128 fp16), ra, adj, first v half ----
        uint4 r4[4];
#pragma unroll
        for (int qg = 0; qg < 4; qg++)
            r4[qg] = __ldg(&Rh4[(head * 4 + qg) * NN + jcol]);
        float ra = __ldg(&g_Ra6[jcol * HH + head]);
        unsigned b = __ldg(&g_adj8[blockIdx.x * NN + jcol]);
        u64 vh[8];
#pragma unroll
        for (int k = 0; k < 8; k++)
            vh[k] = __double_as_longlong(__ldg(&Vp[(size_t)(jpb + k) * 32 + lane]));

        // ---- e phase: fp16x2 HADD2 + abs(LOP) + HFMA2, 4-deep per half ----
#pragma unroll
        for (int ii = 0; ii < I_TILE; ii++) {
            const uint4* lrow = reinterpret_cast<const uint4*>(&l_sh[ii * DIM + head * 32]);
            u32 ea0 = 0u, ea1 = 0u, ea2 = 0u, ea3 = 0u;   // half2 zeros
#pragma unroll
            for (int qg = 0; qg < 4; qg++) {
                uint4 l4 = lrow[qg];
                u32 y0, y1, y2, y3;
                HADD2(y0, l4.x, r4[qg].x);
                HADD2(y1, l4.y, r4[qg].y);
                HADD2(y2, l4.z, r4[qg].z);
                HADD2(y3, l4.w, r4[qg].w);
                y0 &= 0x7FFF7FFFu; y1 &= 0x7FFF7FFFu;     // |.| both halves (ALU)
                y2 &= 0x7FFF7FFFu; y3 &= 0x7FFF7FFFu;
                HFMA2(ea0, ar2h[qg * 4 + 0], y0);
                HFMA2(ea1, ar2h[qg * 4 + 1], y1);
                HFMA2(ea2, ar2h[qg * 4 + 2], y2);
                HFMA2(ea3, ar2h[qg * 4 + 3], y3);
            }
            HADD2(ea0, ea0, ea1);
            HADD2(ea2, ea2, ea3);
            HADD2(ea0, ea0, ea2);
            float2 f2 = __half22float2(*reinterpret_cast<__half2*>(&ea0));
            float e = (la[ii] + ra) + (f2.x + f2.y);
            float p;
            asm("ex2.approx.f32 %0, %1;" : "=f"(p) : "f"(e));
            p = (b & (1u << ii)) ? p : 0.f;
            sl[ii] += p;
            myp[ii * 32 + lane] = p;
        }

        // second v half issued before handoff (hidden by agg first half)
        u64 vh2[8];
#pragma unroll
        for (int k = 0; k < 8; k++)
            vh2[k] = __double_as_longlong(__ldg(&Vp[(size_t)(jpb + 8 + k) * 32 + lane]));
        __syncwarp();

        // ---- agg phase: lane owns d; packed f32x2 over j-pairs ----
#pragma unroll
        for (int q4 = 0; q4 < 4; q4++) {
            u64 v0 = (q4 < 2) ? vh[q4 * 4 + 0] : vh2[(q4 - 2) * 4 + 0];
            u64 v1 = (q4 < 2) ? vh[q4 * 4 + 1] : vh2[(q4 - 2) * 4 + 1];
            u64 v2 = (q4 < 2) ? vh[q4 * 4 + 2] : vh2[(q4 - 2) * 4 + 2];
            u64 v3 = (q4 < 2) ? vh[q4 * 4 + 3] : vh2[(q4 - 2) * 4 + 3];
#pragma unroll
            for (int ii = 0; ii < I_TILE; ii++) {
                ulonglong2 pA = *reinterpret_cast<const ulonglong2*>(&myp[ii * 32 + q4 * 8]);
                ulonglong2 pB = *reinterpret_cast<const ulonglong2*>(&myp[ii * 32 + q4 * 8 + 4]);
                FMA2(acc2[ii], pA.x, v0);
                FMA2(acc2[ii], pA.y, v1);
                FMA2(acc2[ii], pB.x, v2);
                FMA2(acc2[ii], pB.y, v3);
            }
        }
        __syncwarp();
    }

    // ---- horizontal unpack of packed accumulators ----
    float accA[I_TILE];
#pragma unroll
    for (int ii = 0; ii < I_TILE; ii++) {
        float lo, hi;
        UNPACK2(lo, hi, acc2[ii]);
        accA[ii] = lo + hi;
    }

    // ---- cross-warp (js) reduction ----
#pragma unroll
    for (int ii = 0; ii < I_TILE; ii++) {
        float S = sl[ii];
#pragma unroll
        for (int o = 16; o; o >>= 1) S += __shfl_xor_sync(0xffffffffu, S, o);
        sl[ii] = S;
    }
    __syncthreads();                 // everyone done with p_s as p-buffer
#pragma unroll
    for (int ii = 0; ii < I_TILE; ii++) {
        myp[ii * 32 + lane] = accA[ii];          // reuse p_s as acc buffer
        if (lane == 0) sl_s[w * I_TILE + ii] = sl[ii];
    }
    __syncthreads();

    // warp w: head' = w&3, covers ii = (w>>2) and (w>>2)+4
#pragma unroll
    for (int r = 0; r < 2; r++) {
        int ii = (w >> 2) + r * 4;
        int hh = w & 3;
        float acc = 0.f, S = 0.f;
#pragma unroll
        for (int g = 0; g < 4; g++) {
            acc += p_s[((g * 4 + hh) * I_TILE + ii) * 32 + lane];
            S   += sl_s[(g * 4 + hh) * I_TILE + ii];
        }
        o_s[ii * DIM + hh * 32 + lane] = acc * __frcp_rn(S);
    }
    __syncthreads();

    // LayerNorm + ReLU: warps 0..7 handle rows 0..7
    if (w < I_TILE) {
        int i = w;
        float v0 = o_s[i * DIM + lane];
        float v1 = o_s[i * DIM + 32 + lane];
        float v2 = o_s[i * DIM + 64 + lane];
        float v3 = o_s[i * DIM + 96 + lane];
        float sm = (v0 + v1) + (v2 + v3);
        float sq = v0 * v0 + v1 * v1 + v2 * v2 + v3 * v3;
#pragma unroll
        for (int o = 16; o; o >>= 1) {
            sm += __shfl_xor_sync(0xffffffffu, sm, o);
            sq += __shfl_xor_sync(0xffffffffu, sq, o);
        }
        float mean = sm * (1.f / 128.f);
        float var  = sq * (1.f / 128.f) - mean * mean;
        float rstd = rsqrtf(var + 1e-5f);
        float vals[4] = {v0, v1, v2, v3};
#pragma unroll
        for (int k = 0; k < 4; k++) {
            int c = 32 * k + lane;
            float y = (vals[k] - mean) * rstd * __ldg(&ln_g[c]) + __ldg(&ln_b[c]);
            out[(i0 + i) * DIM + c] = fmaxf(y, 0.f);
        }
    }
}

extern "C" void kernel_launch(void* const* d_in, const int* in_sizes, int n_in,
                              void* d_out, int out_size)
{
    const float* h   = (const float*)d_in[0];
    const int*   adj = (const int*)  d_in[1];
    const float* Wl  = (const float*)d_in[2];
    const float* Wr  = (const float*)d_in[3];
    const float* Wv  = (const float*)d_in[4];
    const float* a   = (const float*)d_in[5];
    const float* g   = (const float*)d_in[6];
    const float* b   = (const float*)d_in[7];

    prep_kernel<<<dim3(128, 4), 128>>>(h, adj, Wl, Wr, Wv, a);
    gat_main<<<NN / I_TILE, 512>>>(a, g, b, (float*)d_out);
}